// round 15
// baseline (speedup 1.0000x reference)
#include <cuda_runtime.h>
#include <cuda_bf16.h>

#define T_LEN 1024
#define D_IN  1024
#define H_HID 512
#define G4    2048
#define BATCH 32
#define ROWS  32768          // T*B
#define NCOL  4096           // 2 dirs * 4H

// ---------------- device scratch ----------------
__device__ __align__(256) __nv_bfloat16 g_ahi[(size_t)ROWS * D_IN];  // A hi [row][k]
__device__ __align__(256) __nv_bfloat16 g_alo[(size_t)ROWS * D_IN];  // A lo
__device__ __align__(256) __nv_bfloat16 g_whi[(size_t)NCOL * D_IN];  // W^T hi [col][k]
__device__ __align__(256) __nv_bfloat16 g_wlo[(size_t)NCOL * D_IN];  // W^T lo
__device__ __align__(256) float g_xg[(size_t)NCOL * ROWS];   // input proj, col-major [col][row]
// recurrent h as bf16 hi/lo in SW128 tiled layout [kt=8][b=32][64 k] per dir/buf
__device__ __align__(256) char g_hA[2][2][32768];            // [buf][dir] hi
__device__ __align__(256) char g_hB[2][2][32768];            // [buf][dir] lo
__device__ __align__(256) float g_part[128][T_LEN][BATCH];   // per-block logit partials
__device__ __align__(256) unsigned g_flag[2][64];            // per-block completed-step counters

// ---------------- acquire/release + mbarrier + bulk-copy helpers ----------------
__device__ __forceinline__ unsigned ld_acq(const unsigned* p) {
    unsigned v;
    asm volatile("ld.global.acquire.gpu.u32 %0, [%1];" : "=r"(v) : "l"(p) : "memory");
    return v;
}
__device__ __forceinline__ void st_rel(unsigned* p, unsigned v) {
    asm volatile("st.global.release.gpu.u32 [%0], %1;" :: "l"(p), "r"(v) : "memory");
}
__device__ __forceinline__ unsigned smem_u32(const void* p) {
    unsigned a;
    asm("{ .reg .u64 t; cvta.to.shared.u64 t, %1; cvt.u32.u64 %0, t; }" : "=r"(a) : "l"(p));
    return a;
}
__device__ __forceinline__ void mbar_init(unsigned mbar, unsigned count) {
    asm volatile("mbarrier.init.shared.b64 [%0], %1;" :: "r"(mbar), "r"(count) : "memory");
}
__device__ __forceinline__ void mbar_expect_tx(unsigned mbar, unsigned bytes) {
    asm volatile("mbarrier.arrive.expect_tx.shared.b64 _, [%0], %1;"
                 :: "r"(mbar), "r"(bytes) : "memory");
}
__device__ __forceinline__ void bulk_g2s(unsigned dst_smem, const void* src, unsigned bytes,
                                         unsigned mbar) {
    asm volatile(
        "cp.async.bulk.shared::cta.global.mbarrier::complete_tx::bytes [%0], [%1], %2, [%3];"
        :: "r"(dst_smem), "l"(src), "r"(bytes), "r"(mbar) : "memory");
}
__device__ __forceinline__ void mbar_wait(unsigned mbar, unsigned parity) {
    asm volatile(
        "{\n\t.reg .pred P;\n"
        "W%=:\n\t"
        "mbarrier.try_wait.parity.acquire.cta.shared::cta.b64 P, [%0], %1, 0x989680;\n\t"
        "@P bra D%=;\n\t"
        "bra W%=;\n"
        "D%=:\n\t}"
        :: "r"(mbar), "r"(parity) : "memory");
}

// ---------------- mma / ldmatrix / cp.async helpers (sm_80-era, sm_103-safe) ----------
__device__ __forceinline__ void ldsm_x4(unsigned& r0, unsigned& r1, unsigned& r2, unsigned& r3,
                                        unsigned addr) {
    asm volatile("ldmatrix.sync.aligned.m8n8.x4.shared.b16 {%0,%1,%2,%3}, [%4];"
                 : "=r"(r0), "=r"(r1), "=r"(r2), "=r"(r3) : "r"(addr));
}
__device__ __forceinline__ void mma_bf16(float* d, unsigned a0, unsigned a1, unsigned a2,
                                         unsigned a3, unsigned b0, unsigned b1) {
    asm volatile(
        "mma.sync.aligned.m16n8k16.row.col.f32.bf16.bf16.f32 "
        "{%0,%1,%2,%3}, {%4,%5,%6,%7}, {%8,%9}, {%0,%1,%2,%3};"
        : "+f"(d[0]), "+f"(d[1]), "+f"(d[2]), "+f"(d[3])
        : "r"(a0), "r"(a1), "r"(a2), "r"(a3), "r"(b0), "r"(b1));
}
__device__ __forceinline__ void cp16(unsigned dst, const void* src) {
    asm volatile("cp.async.cg.shared.global [%0], [%1], 16;" :: "r"(dst), "l"(src));
}
__device__ __forceinline__ void cp_commit() { asm volatile("cp.async.commit_group;"); }
template <int N>
__device__ __forceinline__ void cp_wait() { asm volatile("cp.async.wait_group %0;" :: "n"(N)); }

#define SWZ(off) ((off) ^ (((off) >> 3) & 0x70))

// ---------------- kernel 1: zero recurrent state + flags ----------------
__global__ void zero_state_kernel() {
    int i = blockIdx.x * blockDim.x + threadIdx.x;       // 65536 threads
    if (i < 32768) ((unsigned*)g_hA)[i] = 0u;
    else           ((unsigned*)g_hB)[i - 32768] = 0u;
    if (i < 128) ((unsigned*)g_flag)[i] = 0u;
}

// ---------------- kernel 2a: x -> bf16 hi/lo, row = t*32+b, k-major ----------------
__global__ void conv_x_kernel(const float* __restrict__ x) {
    int idx = blockIdx.x * blockDim.x + threadIdx.x;
    int row = idx >> 7;
    int kc  = (idx & 127) * 8;
    int b = row & 31, t = row >> 5;
    const float4* src = (const float4*)(x + ((size_t)b * T_LEN + t) * D_IN + kc);
    float4 v0 = src[0], v1 = src[1];
    float vs[8] = {v0.x, v0.y, v0.z, v0.w, v1.x, v1.y, v1.z, v1.w};
    __nv_bfloat16 hi[8], lo[8];
#pragma unroll
    for (int i = 0; i < 8; ++i) {
        hi[i] = __float2bfloat16_rn(vs[i]);
        lo[i] = __float2bfloat16_rn(vs[i] - __bfloat162float(hi[i]));
    }
    *(uint4*)(g_ahi + (size_t)row * D_IN + kc) = *(uint4*)hi;
    *(uint4*)(g_alo + (size_t)row * D_IN + kc) = *(uint4*)lo;
}

// ---------------- kernel 2b: W [k][col] -> W^T bf16 hi/lo [col][k] ----------------
__global__ void conv_w_kernel(const float* __restrict__ Wx_f, const float* __restrict__ Wx_b) {
    __shared__ float tile[32][33];
    int cblk = blockIdx.x * 32;
    int kblk = blockIdx.y * 32;
    int tid = threadIdx.x;
    int cl = tid & 31, kr = tid >> 5;
#pragma unroll
    for (int i = 0; i < 4; ++i) {
        int kl = kr + i * 8;
        int col = cblk + cl;
        const float* W = (col < G4) ? Wx_f : Wx_b;
        int c2 = (col < G4) ? col : col - G4;
        tile[kl][cl] = W[(size_t)(kblk + kl) * G4 + c2];
    }
    __syncthreads();
    int kl2 = tid & 31, cr = tid >> 5;
#pragma unroll
    for (int i = 0; i < 4; ++i) {
        int cl2 = cr + i * 8;
        float v = tile[kl2][cl2];
        __nv_bfloat16 hi = __float2bfloat16_rn(v);
        __nv_bfloat16 lo = __float2bfloat16_rn(v - __bfloat162float(hi));
        size_t o = (size_t)(cblk + cl2) * D_IN + kblk + kl2;
        g_whi[o] = hi;
        g_wlo[o] = lo;
    }
}

// ---------------- kernel 3: xg = A @ W^T via mma.sync bf16 3-split (proven R12) -------
#define GSM_TOT 131072

__global__ void __launch_bounds__(256, 1)
mma_gemm_kernel() {
    extern __shared__ char smg[];
    const int tid = threadIdx.x, lane = tid & 31, wid = tid >> 5;
    const int cb = blockIdx.x, rb = blockIdx.y;
    const unsigned sbase = smem_u32(smg);
    const int warp_m = wid >> 1, warp_n = wid & 1;

    const __nv_bfloat16* src0 = g_ahi + (size_t)rb * 128 * D_IN;
    const __nv_bfloat16* src1 = g_alo + (size_t)rb * 128 * D_IN;
    const __nv_bfloat16* src2 = g_whi + (size_t)cb * 128 * D_IN;
    const __nv_bfloat16* src3 = g_wlo + (size_t)cb * 128 * D_IN;

    auto load_stage = [&](int kt, int buf) {
        unsigned dbase = sbase + buf * 65536;
#pragma unroll
        for (int i = 0; i < 16; ++i) {
            int c = tid + i * 256;
            int m = c >> 10, cc = c & 1023;
            int row = cc >> 3, kc = cc & 7;
            const __nv_bfloat16* s =
                (m == 0 ? src0 : m == 1 ? src1 : m == 2 ? src2 : src3)
                + (size_t)row * D_IN + kt * 64 + kc * 8;
            unsigned off = (unsigned)(row * 128 + kc * 16);
            cp16(dbase + m * 16384 + SWZ(off), s);
        }
    };

    float acc[2][8][4];
#pragma unroll
    for (int mt = 0; mt < 2; ++mt)
#pragma unroll
        for (int nt = 0; nt < 8; ++nt)
#pragma unroll
            for (int r = 0; r < 4; ++r) acc[mt][nt][r] = 0.0f;

    const unsigned la_row = lane & 15;
    const unsigned la_kh  = lane >> 4;
    const unsigned lb_row = (lane & 7) + ((lane >> 4) << 3);
    const unsigned lb_kh  = (lane >> 3) & 1;

    load_stage(0, 0); cp_commit();

    for (int ti = 0; ti < 16; ++ti) {
        const int buf = ti & 1;
        if (ti + 1 < 16) {
            load_stage(ti + 1, buf ^ 1); cp_commit();
            cp_wait<1>();
        } else {
            cp_wait<0>();
        }
        __syncthreads();

        const unsigned base = sbase + buf * 65536;
#pragma unroll
        for (int sp = 0; sp < 3; ++sp) {
            const unsigned abase = base + (sp == 2 ? 16384 : 0);
            const unsigned wbase = base + (sp == 1 ? 49152 : 32768);
#pragma unroll
            for (int k16 = 0; k16 < 4; ++k16) {
                unsigned a[2][4];
#pragma unroll
                for (int mt = 0; mt < 2; ++mt) {
                    unsigned off = (unsigned)((warp_m * 32 + mt * 16 + la_row) * 128
                                              + k16 * 32 + la_kh * 16);
                    ldsm_x4(a[mt][0], a[mt][1], a[mt][2], a[mt][3], abase + SWZ(off));
                }
#pragma unroll
                for (int np = 0; np < 4; ++np) {
                    unsigned b0, b1, b2, b3;
                    unsigned off = (unsigned)((warp_n * 64 + np * 16 + lb_row) * 128
                                              + k16 * 32 + lb_kh * 16);
                    ldsm_x4(b0, b1, b2, b3, wbase + SWZ(off));
#pragma unroll
                    for (int mt = 0; mt < 2; ++mt) {
                        mma_bf16(acc[mt][np * 2],     a[mt][0], a[mt][1], a[mt][2], a[mt][3], b0, b1);
                        mma_bf16(acc[mt][np * 2 + 1], a[mt][0], a[mt][1], a[mt][2], a[mt][3], b2, b3);
                    }
                }
            }
        }
        __syncthreads();
    }

    const int r0 = rb * 128 + warp_m * 32 + (lane >> 2);
#pragma unroll
    for (int mt = 0; mt < 2; ++mt)
#pragma unroll
        for (int nt = 0; nt < 8; ++nt) {
            size_t col = (size_t)cb * 128 + warp_n * 64 + nt * 8 + 2 * (lane & 3);
            int row = r0 + mt * 16;
            g_xg[col * ROWS + row]           = acc[mt][nt][0];
            g_xg[(col + 1) * ROWS + row]     = acc[mt][nt][1];
            g_xg[col * ROWS + row + 8]       = acc[mt][nt][2];
            g_xg[(col + 1) * ROWS + row + 8] = acc[mt][nt][3];
        }
}

// ---------------- kernel 4: persistent recurrent phase, tensor-core k-loop ----------
// R13 structure; barrier simplified: warp 0 of EVERY block polls all 64 dir flags
// directly (2 flags/lane, one coalesced 256B read per round) — no checker hop.
#define LSM_PART 131072
#define LSM_PSUM 163840
#define LSM_MBAR 164864
#define LSM_TOT  164896

__global__ void __launch_bounds__(256, 1)
lstm_kernel(const float* __restrict__ Wh_f, const float* __restrict__ Wh_b,
            const float* __restrict__ b_f,  const float* __restrict__ b_b,
            const float* __restrict__ Wfc)
{
    extern __shared__ char smg[];
    float* part = (float*)(smg + LSM_PART);    // [w 8][cc 32][b 32]
    float* psum = (float*)(smg + LSM_PSUM);

    const int tid  = threadIdx.x;
    const int lane = tid & 31;
    const int w    = tid >> 5;                 // warp 0..7 = k-slice
    const int blk  = blockIdx.x;
    const int dir  = blk >> 6;
    const int j0   = (blk & 63) * 8;

    const int u = tid >> 5;                    // hidden unit 0..7
    const int b = tid & 31;                    // batch

    const float* Wh   = dir ? Wh_b : Wh_f;
    const float* bias = dir ? b_b  : b_f;

    const unsigned sbase = smem_u32(smg);
    const unsigned mbar  = smem_u32(smg + LSM_MBAR);
    if (tid == 0) mbar_init(mbar, 1);

    // convert Wh slice -> smem bf16 hi/lo, SW128 tiled [kt][cc][64k]
    for (int e = tid; e < 512 * 32; e += 256) {
        int k = e >> 5, cc = e & 31;
        float v = Wh[(size_t)k * G4 + (cc >> 3) * 512 + j0 + (cc & 7)];
        __nv_bfloat16 hi = __float2bfloat16_rn(v);
        __nv_bfloat16 lo = __float2bfloat16_rn(v - __bfloat162float(hi));
        int kt = k >> 6, kc = k & 63;
        unsigned byte = (unsigned)(kt * 4096 + cc * 128 + kc * 2);
        *(__nv_bfloat16*)(smg + 65536 + SWZ(byte)) = hi;
        *(__nv_bfloat16*)(smg + 98304 + SWZ(byte)) = lo;
    }

    float biasr[4];
#pragma unroll
    for (int g = 0; g < 4; ++g) biasr[g] = bias[g * 512 + j0 + u];
    const float wfc = Wfc[dir * H_HID + j0 + u];

    // ldmatrix lane offsets (same as proven GEMM)
    const unsigned la_row = lane & 15;
    const unsigned la_kh  = lane >> 4;
    const unsigned lb_row = (lane & 7) + ((lane >> 4) << 3);
    const unsigned lb_kh  = (lane >> 3) & 1;
    const unsigned kt_off = (unsigned)(w * 4096);

    // producer write address for this thread's h element (j = j0+u)
    const int jj = j0 + u;
    const unsigned h_byte = SWZ((unsigned)((jj >> 6) * 4096 + b * 128 + (jj & 63) * 2));

    // warp-0 poll addresses: lane covers flags 2*lane and 2*lane+1
    const unsigned* f0 = &g_flag[dir][lane * 2];
    const unsigned* f1 = &g_flag[dir][lane * 2 + 1];

    float cstate = 0.0f;
    __syncthreads();

    for (int s = 0; s < T_LEN; ++s) {
        const int t = dir ? (T_LEN - 1 - s) : s;

        // prefetch xg (independent of h)
        float xgv[4];
#pragma unroll
        for (int g = 0; g < 4; ++g)
            xgv[g] = __ldg(g_xg + (size_t)(dir * G4 + g * 512 + j0 + u) * ROWS + t * 32 + b);

        // warp 0: wait for all 64 producers of this dir, then kick the bulk copy
        if (w == 0) {
            if (s > 0) {
                bool ok;
                do {
                    ok = (ld_acq(f0) >= (unsigned)s) && (ld_acq(f1) >= (unsigned)s);
                } while (!__all_sync(0xffffffffu, ok));
            }
            if (lane == 0) {
                mbar_expect_tx(mbar, 65536u);
                bulk_g2s(sbase,          g_hA[s & 1][dir], 32768u, mbar);
                bulk_g2s(sbase + 32768u, g_hB[s & 1][dir], 32768u, mbar);
            }
        }
        mbar_wait(mbar, s & 1);

        // tensor k-phase: warp w covers kt=w (4 k16 tiles), 3 splits
        float acc[2][4][4];
#pragma unroll
        for (int mt = 0; mt < 2; ++mt)
#pragma unroll
            for (int nt = 0; nt < 4; ++nt)
#pragma unroll
                for (int r = 0; r < 4; ++r) acc[mt][nt][r] = 0.0f;

#pragma unroll
        for (int sp = 0; sp < 3; ++sp) {
            const unsigned abase = sbase + (sp == 2 ? 32768u : 0u);
            const unsigned wbase = sbase + 65536u + (sp == 1 ? 32768u : 0u);
#pragma unroll
            for (int k16 = 0; k16 < 4; ++k16) {
                unsigned a[2][4];
#pragma unroll
                for (int mt = 0; mt < 2; ++mt) {
                    unsigned off = kt_off + (mt * 16 + la_row) * 128 + k16 * 32 + la_kh * 16;
                    ldsm_x4(a[mt][0], a[mt][1], a[mt][2], a[mt][3], abase + SWZ(off));
                }
#pragma unroll
                for (int np = 0; np < 2; ++np) {
                    unsigned b0, b1, b2, b3;
                    unsigned off = kt_off + (np * 16 + lb_row) * 128 + k16 * 32 + lb_kh * 16;
                    ldsm_x4(b0, b1, b2, b3, wbase + SWZ(off));
#pragma unroll
                    for (int mt = 0; mt < 2; ++mt) {
                        mma_bf16(acc[mt][np * 2],     a[mt][0], a[mt][1], a[mt][2], a[mt][3], b0, b1);
                        mma_bf16(acc[mt][np * 2 + 1], a[mt][0], a[mt][1], a[mt][2], a[mt][3], b2, b3);
                    }
                }
            }
        }
        // write warp partials: part[w][cc][b]
        {
            const int brow = lane >> 2;
            const int c0 = (lane & 3) * 2;
            float* pp = part + w * 1024;
#pragma unroll
            for (int mt = 0; mt < 2; ++mt)
#pragma unroll
                for (int nt = 0; nt < 4; ++nt) {
                    int cc = nt * 8 + c0;
                    int bb = mt * 16 + brow;
                    pp[cc * 32 + bb]            = acc[mt][nt][0];
                    pp[(cc + 1) * 32 + bb]      = acc[mt][nt][1];
                    pp[cc * 32 + bb + 8]        = acc[mt][nt][2];
                    pp[(cc + 1) * 32 + bb + 8]  = acc[mt][nt][3];
                }
        }
        __syncthreads();

        // epilogue: thread (u, b) computes cell update
        {
            float gate[4];
#pragma unroll
            for (int g = 0; g < 4; ++g) {
                float sum = xgv[g] + biasr[g];
                const float* pp = part + (g * 8 + u) * 32 + b;
#pragma unroll
                for (int sl = 0; sl < 8; ++sl) sum += pp[sl * 1024];
                gate[g] = sum;
            }
            float iv = 1.0f / (1.0f + __expf(-gate[0]));
            float fv = 1.0f / (1.0f + __expf(-gate[1]));
            float gv = tanhf(gate[2]);
            float ov = 1.0f / (1.0f + __expf(-gate[3]));
            cstate = fv * cstate + iv * gv;
            float hv = ov * tanhf(cstate);
            // publish h as bf16 hi/lo into swizzled tiled layout
            __nv_bfloat16 hhi = __float2bfloat16_rn(hv);
            __nv_bfloat16 hlo = __float2bfloat16_rn(hv - __bfloat162float(hhi));
            *(__nv_bfloat16*)(g_hA[(s + 1) & 1][dir] + h_byte) = hhi;
            *(__nv_bfloat16*)(g_hB[(s + 1) & 1][dir] + h_byte) = hlo;
            psum[tid] = hv * wfc;
        }
        __syncthreads();
        // publish step completion (h writes ordered by syncthreads before release)
        if (tid == 64 && s + 1 < T_LEN)
            st_rel(&g_flag[dir][blk & 63], (unsigned)(s + 1));
        if (tid < 32) {
            float tot = 0.0f;
#pragma unroll
            for (int uu = 0; uu < 8; ++uu) tot += psum[tid + uu * 32];
            g_part[blk][t][tid] = tot;
        }
    }
}

// ---------------- kernel 5: reduce partials + sigmoid ----------------
__global__ void finalize_kernel(const float* __restrict__ b_fc, float* __restrict__ out) {
    int g = blockIdx.x * blockDim.x + threadIdx.x;
    if (g >= T_LEN * BATCH) return;
    int t = g >> 5, b = g & 31;
    float acc = b_fc[0];
    const float* p = &g_part[0][t][b];
#pragma unroll 8
    for (int blk = 0; blk < 128; ++blk)
        acc += p[(size_t)blk * T_LEN * BATCH];
    out[(size_t)b * T_LEN + t] = 1.0f / (1.0f + __expf(-acc));
}

// ---------------- launcher ----------------
extern "C" void kernel_launch(void* const* d_in, const int* in_sizes, int n_in,
                              void* d_out, int out_size) {
    const float* x    = (const float*)d_in[0];
    const float* Wx_f = (const float*)d_in[1];
    const float* Wh_f = (const float*)d_in[2];
    const float* b_f  = (const float*)d_in[3];
    const float* Wx_b = (const float*)d_in[4];
    const float* Wh_b = (const float*)d_in[5];
    const float* b_b  = (const float*)d_in[6];
    const float* Wfc  = (const float*)d_in[7];
    const float* bfc  = (const float*)d_in[8];
    float* out = (float*)d_out;
    (void)in_sizes; (void)n_in; (void)out_size;

    cudaFuncSetAttribute(mma_gemm_kernel, cudaFuncAttributeMaxDynamicSharedMemorySize, GSM_TOT);
    cudaFuncSetAttribute(lstm_kernel, cudaFuncAttributeMaxDynamicSharedMemorySize, LSM_TOT);

    zero_state_kernel<<<256, 256>>>();
    conv_x_kernel<<<ROWS * D_IN / 8 / 256, 256>>>(x);
    conv_w_kernel<<<dim3(NCOL / 32, D_IN / 32), 256>>>(Wx_f, Wx_b);
    mma_gemm_kernel<<<dim3(32, 256), 256, GSM_TOT>>>();
    lstm_kernel<<<128, 256, LSM_TOT>>>(Wh_f, Wh_b, b_f, b_b, Wfc);
    finalize_kernel<<<128, 256>>>(bfc, out);
}

// round 17
// speedup vs baseline: 1.9337x; 1.9337x over previous
#include <cuda_runtime.h>
#include <cuda_bf16.h>

#define T_LEN 1024
#define D_IN  1024
#define H_HID 512
#define G4    2048
#define BATCH 32
#define ROWS  32768          // T*B
#define NCOL  4096           // 2 dirs * 4H

// ---------------- device scratch ----------------
__device__ __align__(256) __nv_bfloat16 g_ahi[(size_t)ROWS * D_IN];  // A hi [row][k]
__device__ __align__(256) __nv_bfloat16 g_alo[(size_t)ROWS * D_IN];  // A lo
__device__ __align__(256) __nv_bfloat16 g_whi[(size_t)NCOL * D_IN];  // W^T hi [col][k]
__device__ __align__(256) __nv_bfloat16 g_wlo[(size_t)NCOL * D_IN];  // W^T lo
__device__ __align__(256) float g_xg[(size_t)NCOL * ROWS];   // input proj, col-major [col][row]
// recurrent h in mma-fragment-major layout, bf16:
//   u32 idx = ((w*2+mt)*4+k16)*128 + r*32 + lane  (idx < 8192)
//   hi plane bytes [0, 32768), lo plane bytes [32768, 65536)
__device__ __align__(256) char g_hF[2][2][65536];            // [buf][dir]
__device__ __align__(256) float g_part[128][T_LEN][BATCH];   // per-block logit partials
__device__ __align__(256) unsigned g_flag[2][64];            // per-block completed-step counters
__device__ unsigned g_gen2[2];                               // per-dir published generation

// ---------------- acquire/release helpers ----------------
__device__ __forceinline__ unsigned ld_acq(const unsigned* p) {
    unsigned v;
    asm volatile("ld.global.acquire.gpu.u32 %0, [%1];" : "=r"(v) : "l"(p) : "memory");
    return v;
}
__device__ __forceinline__ void st_rel(unsigned* p, unsigned v) {
    asm volatile("st.global.release.gpu.u32 [%0], %1;" :: "l"(p), "r"(v) : "memory");
}
__device__ __forceinline__ unsigned ldcg(const void* p) {
    unsigned v;
    asm volatile("ld.global.cg.b32 %0, [%1];" : "=r"(v) : "l"(p) : "memory");
    return v;
}
__device__ __forceinline__ unsigned smem_u32(const void* p) {
    unsigned a;
    asm("{ .reg .u64 t; cvta.to.shared.u64 t, %1; cvt.u32.u64 %0, t; }" : "=r"(a) : "l"(p));
    return a;
}

// ---------------- mma / ldmatrix / cp.async helpers (sm_80-era, sm_103-safe) ----------
__device__ __forceinline__ void ldsm_x4(unsigned& r0, unsigned& r1, unsigned& r2, unsigned& r3,
                                        unsigned addr) {
    asm volatile("ldmatrix.sync.aligned.m8n8.x4.shared.b16 {%0,%1,%2,%3}, [%4];"
                 : "=r"(r0), "=r"(r1), "=r"(r2), "=r"(r3) : "r"(addr));
}
__device__ __forceinline__ void mma_bf16(float* d, unsigned a0, unsigned a1, unsigned a2,
                                         unsigned a3, unsigned b0, unsigned b1) {
    asm volatile(
        "mma.sync.aligned.m16n8k16.row.col.f32.bf16.bf16.f32 "
        "{%0,%1,%2,%3}, {%4,%5,%6,%7}, {%8,%9}, {%0,%1,%2,%3};"
        : "+f"(d[0]), "+f"(d[1]), "+f"(d[2]), "+f"(d[3])
        : "r"(a0), "r"(a1), "r"(a2), "r"(a3), "r"(b0), "r"(b1));
}
__device__ __forceinline__ void cp16(unsigned dst, const void* src) {
    asm volatile("cp.async.cg.shared.global [%0], [%1], 16;" :: "r"(dst), "l"(src));
}
__device__ __forceinline__ void cp_commit() { asm volatile("cp.async.commit_group;"); }
template <int N>
__device__ __forceinline__ void cp_wait() { asm volatile("cp.async.wait_group %0;" :: "n"(N)); }

#define SWZ(off) ((off) ^ (((off) >> 3) & 0x70))

// ---------------- kernel 1: zero recurrent state + flags ----------------
__global__ void zero_state_kernel() {
    int i = blockIdx.x * blockDim.x + threadIdx.x;       // 65536 threads
    ((unsigned*)g_hF)[i] = 0u;                           // 262144 B = 65536 u32
    if (i < 128) ((unsigned*)g_flag)[i] = 0u;
    if (i < 2)   g_gen2[i] = 0u;
}

// ---------------- kernel 2a: x -> bf16 hi/lo, row = t*32+b, k-major ----------------
__global__ void conv_x_kernel(const float* __restrict__ x) {
    int idx = blockIdx.x * blockDim.x + threadIdx.x;
    int row = idx >> 7;
    int kc  = (idx & 127) * 8;
    int b = row & 31, t = row >> 5;
    const float4* src = (const float4*)(x + ((size_t)b * T_LEN + t) * D_IN + kc);
    float4 v0 = src[0], v1 = src[1];
    float vs[8] = {v0.x, v0.y, v0.z, v0.w, v1.x, v1.y, v1.z, v1.w};
    __nv_bfloat16 hi[8], lo[8];
#pragma unroll
    for (int i = 0; i < 8; ++i) {
        hi[i] = __float2bfloat16_rn(vs[i]);
        lo[i] = __float2bfloat16_rn(vs[i] - __bfloat162float(hi[i]));
    }
    *(uint4*)(g_ahi + (size_t)row * D_IN + kc) = *(uint4*)hi;
    *(uint4*)(g_alo + (size_t)row * D_IN + kc) = *(uint4*)lo;
}

// ---------------- kernel 2b: W [k][col] -> W^T bf16 hi/lo [col][k] ----------------
__global__ void conv_w_kernel(const float* __restrict__ Wx_f, const float* __restrict__ Wx_b) {
    __shared__ float tile[32][33];
    int cblk = blockIdx.x * 32;
    int kblk = blockIdx.y * 32;
    int tid = threadIdx.x;
    int cl = tid & 31, kr = tid >> 5;
#pragma unroll
    for (int i = 0; i < 4; ++i) {
        int kl = kr + i * 8;
        int col = cblk + cl;
        const float* W = (col < G4) ? Wx_f : Wx_b;
        int c2 = (col < G4) ? col : col - G4;
        tile[kl][cl] = W[(size_t)(kblk + kl) * G4 + c2];
    }
    __syncthreads();
    int kl2 = tid & 31, cr = tid >> 5;
#pragma unroll
    for (int i = 0; i < 4; ++i) {
        int cl2 = cr + i * 8;
        float v = tile[kl2][cl2];
        __nv_bfloat16 hi = __float2bfloat16_rn(v);
        __nv_bfloat16 lo = __float2bfloat16_rn(v - __bfloat162float(hi));
        size_t o = (size_t)(cblk + cl2) * D_IN + kblk + kl2;
        g_whi[o] = hi;
        g_wlo[o] = lo;
    }
}

// ---------------- kernel 3: xg = A @ W^T via mma.sync bf16 3-split (proven R12) -------
#define GSM_TOT 131072

__global__ void __launch_bounds__(256, 1)
mma_gemm_kernel() {
    extern __shared__ char smg[];
    const int tid = threadIdx.x, lane = tid & 31, wid = tid >> 5;
    const int cb = blockIdx.x, rb = blockIdx.y;
    const unsigned sbase = smem_u32(smg);
    const int warp_m = wid >> 1, warp_n = wid & 1;

    const __nv_bfloat16* src0 = g_ahi + (size_t)rb * 128 * D_IN;
    const __nv_bfloat16* src1 = g_alo + (size_t)rb * 128 * D_IN;
    const __nv_bfloat16* src2 = g_whi + (size_t)cb * 128 * D_IN;
    const __nv_bfloat16* src3 = g_wlo + (size_t)cb * 128 * D_IN;

    auto load_stage = [&](int kt, int buf) {
        unsigned dbase = sbase + buf * 65536;
#pragma unroll
        for (int i = 0; i < 16; ++i) {
            int c = tid + i * 256;
            int m = c >> 10, cc = c & 1023;
            int row = cc >> 3, kc = cc & 7;
            const __nv_bfloat16* s =
                (m == 0 ? src0 : m == 1 ? src1 : m == 2 ? src2 : src3)
                + (size_t)row * D_IN + kt * 64 + kc * 8;
            unsigned off = (unsigned)(row * 128 + kc * 16);
            cp16(dbase + m * 16384 + SWZ(off), s);
        }
    };

    float acc[2][8][4];
#pragma unroll
    for (int mt = 0; mt < 2; ++mt)
#pragma unroll
        for (int nt = 0; nt < 8; ++nt)
#pragma unroll
            for (int r = 0; r < 4; ++r) acc[mt][nt][r] = 0.0f;

    const unsigned la_row = lane & 15;
    const unsigned la_kh  = lane >> 4;
    const unsigned lb_row = (lane & 7) + ((lane >> 4) << 3);
    const unsigned lb_kh  = (lane >> 3) & 1;

    load_stage(0, 0); cp_commit();

    for (int ti = 0; ti < 16; ++ti) {
        const int buf = ti & 1;
        if (ti + 1 < 16) {
            load_stage(ti + 1, buf ^ 1); cp_commit();
            cp_wait<1>();
        } else {
            cp_wait<0>();
        }
        __syncthreads();

        const unsigned base = sbase + buf * 65536;
#pragma unroll
        for (int sp = 0; sp < 3; ++sp) {
            const unsigned abase = base + (sp == 2 ? 16384 : 0);
            const unsigned wbase = base + (sp == 1 ? 49152 : 32768);
#pragma unroll
            for (int k16 = 0; k16 < 4; ++k16) {
                unsigned a[2][4];
#pragma unroll
                for (int mt = 0; mt < 2; ++mt) {
                    unsigned off = (unsigned)((warp_m * 32 + mt * 16 + la_row) * 128
                                              + k16 * 32 + la_kh * 16);
                    ldsm_x4(a[mt][0], a[mt][1], a[mt][2], a[mt][3], abase + SWZ(off));
                }
#pragma unroll
                for (int np = 0; np < 4; ++np) {
                    unsigned b0, b1, b2, b3;
                    unsigned off = (unsigned)((warp_n * 64 + np * 16 + lb_row) * 128
                                              + k16 * 32 + lb_kh * 16);
                    ldsm_x4(b0, b1, b2, b3, wbase + SWZ(off));
#pragma unroll
                    for (int mt = 0; mt < 2; ++mt) {
                        mma_bf16(acc[mt][np * 2],     a[mt][0], a[mt][1], a[mt][2], a[mt][3], b0, b1);
                        mma_bf16(acc[mt][np * 2 + 1], a[mt][0], a[mt][1], a[mt][2], a[mt][3], b2, b3);
                    }
                }
            }
        }
        __syncthreads();
    }

    const int r0 = rb * 128 + warp_m * 32 + (lane >> 2);
#pragma unroll
    for (int mt = 0; mt < 2; ++mt)
#pragma unroll
        for (int nt = 0; nt < 8; ++nt) {
            size_t col = (size_t)cb * 128 + warp_n * 64 + nt * 8 + 2 * (lane & 3);
            int row = r0 + mt * 16;
            g_xg[col * ROWS + row]           = acc[mt][nt][0];
            g_xg[(col + 1) * ROWS + row]     = acc[mt][nt][1];
            g_xg[col * ROWS + row + 8]       = acc[mt][nt][2];
            g_xg[(col + 1) * ROWS + row + 8] = acc[mt][nt][3];
        }
}

// ---------------- kernel 4: persistent recurrent phase ----------------
// 128 blocks, 256 threads. Warp w owns k-slice [64w,64w+64).
// W fragments in registers (loaded once). h fragments via COALESCED ld.global.cg
// from fragment-major layout (one 128B line per fragment reg).
// Barrier: proven R13 checker->gen. No smem staging, no mbarrier, no ldmatrix.
#define LSM_TOT 33792    // part 32KB + psum 1KB

__global__ void __launch_bounds__(256, 1)
lstm_kernel(const float* __restrict__ Wh_f, const float* __restrict__ Wh_b,
            const float* __restrict__ b_f,  const float* __restrict__ b_b,
            const float* __restrict__ Wfc)
{
    extern __shared__ char smg[];
    float* part = (float*)smg;                 // [w 8][cc 32][b 32]
    float* psum = (float*)(smg + 32768);

    const int tid  = threadIdx.x;
    const int lane = tid & 31;
    const int w    = tid >> 5;                 // warp 0..7 = k-slice
    const int blk  = blockIdx.x;
    const int dir  = blk >> 6;
    const int j0   = (blk & 63) * 8;
    const bool checker = ((blk & 63) == 0);

    const int u = tid >> 5;                    // hidden unit 0..7
    const int b = tid & 31;                    // batch

    const float* Wh   = dir ? Wh_b : Wh_f;
    const float* bias = dir ? b_b  : b_f;

    // ---- W mma B-fragments in registers (verified in R14) ----
    unsigned wbhi[2][4][4], wblo[2][4][4];
    {
        const int n_base = lane >> 2;
        const int k_base = w * 64 + (lane & 3) * 2;
#pragma unroll
        for (int np = 0; np < 2; ++np)
#pragma unroll
            for (int k16 = 0; k16 < 4; ++k16)
#pragma unroll
                for (int r = 0; r < 4; ++r) {
                    int cc = np * 16 + n_base + ((r >> 1) << 3);
                    int gc = (cc >> 3) * 512 + j0 + (cc & 7);
                    int k  = k_base + k16 * 16 + ((r & 1) << 3);
                    float v0 = Wh[(size_t)k * G4 + gc];
                    float v1 = Wh[(size_t)(k + 1) * G4 + gc];
                    __nv_bfloat16 h0 = __float2bfloat16_rn(v0);
                    __nv_bfloat16 h1 = __float2bfloat16_rn(v1);
                    __nv_bfloat16 l0 = __float2bfloat16_rn(v0 - __bfloat162float(h0));
                    __nv_bfloat16 l1 = __float2bfloat16_rn(v1 - __bfloat162float(h1));
                    unsigned uh0 = *(unsigned short*)&h0, uh1 = *(unsigned short*)&h1;
                    unsigned ul0 = *(unsigned short*)&l0, ul1 = *(unsigned short*)&l1;
                    wbhi[np][k16][r] = (uh1 << 16) | uh0;
                    wblo[np][k16][r] = (ul1 << 16) | ul0;
                }
    }

    float biasr[4];
#pragma unroll
    for (int g = 0; g < 4; ++g) biasr[g] = bias[g * 512 + j0 + u];
    const float wfc = Wfc[dir * H_HID + j0 + u];

    // consumer fragment base: u32 idx = ((w*2+mt)*4+k16)*128 + r*32 + lane
    const unsigned frag_base = (unsigned)((w * 8) * 128 + lane) * 4;   // bytes, mt=k16=r=0

    // producer store address for h[b][j], j = j0+u
    const int jp = j0 + u;
    const int kl = jp & 15, bl = b & 15;
    const unsigned st_idx =
        (unsigned)((((jp >> 6) * 2 + (b >> 4)) * 4 + ((jp >> 4) & 3)) * 128
                   + ((kl >= 8 ? 2 : 0) + (bl >= 8 ? 1 : 0)) * 32
                   + (bl & 7) * 4 + ((kl & 7) >> 1));
    const unsigned st_byte = st_idx * 4 + (kl & 1) * 2;

    float cstate = 0.0f;
    __syncthreads();

    for (int s = 0; s < T_LEN; ++s) {
        const int t = dir ? (T_LEN - 1 - s) : s;

        // prefetch xg (independent of h)
        float xgv[4];
#pragma unroll
        for (int g = 0; g < 4; ++g)
            xgv[g] = __ldg(g_xg + (size_t)(dir * G4 + g * 512 + j0 + u) * ROWS + t * 32 + b);

        // inter-block sync: flags -> checker -> gen (proven R13 pattern)
        if (s > 0) {
            if (checker) {
                if (tid < 32) {
                    const unsigned* fa = &g_flag[dir][tid];
                    const unsigned* fb = &g_flag[dir][tid + 32];
                    bool ok;
                    do {
                        ok = (ld_acq(fa) >= (unsigned)s) && (ld_acq(fb) >= (unsigned)s);
                    } while (!__all_sync(0xffffffffu, ok));
                    if (tid == 0) st_rel(&g_gen2[dir], (unsigned)s);
                }
            } else {
                if (tid == 0) {
                    while (ld_acq(&g_gen2[dir]) < (unsigned)s) { }
                }
            }
            __syncthreads();
        }

        // load h fragments: 64 coalesced LDG.32 (.cg), one 128B line each
        const char* hp = g_hF[s & 1][dir];
        unsigned ahi[2][4][4], alo[2][4][4];
#pragma unroll
        for (int mt = 0; mt < 2; ++mt)
#pragma unroll
            for (int k16 = 0; k16 < 4; ++k16)
#pragma unroll
                for (int r = 0; r < 4; ++r) {
                    unsigned off = frag_base + (unsigned)(((mt * 4 + k16) * 128 + r * 32) * 4);
                    ahi[mt][k16][r] = ldcg(hp + off);
                    alo[mt][k16][r] = ldcg(hp + 32768 + off);
                }

        // mma: 3 splits (Ahi*Whi + Ahi*Wlo + Alo*Whi), 96 HMMA
        float acc[2][4][4];
#pragma unroll
        for (int mt = 0; mt < 2; ++mt)
#pragma unroll
            for (int nt = 0; nt < 4; ++nt)
#pragma unroll
                for (int r = 0; r < 4; ++r) acc[mt][nt][r] = 0.0f;

#pragma unroll
        for (int k16 = 0; k16 < 4; ++k16)
#pragma unroll
            for (int np = 0; np < 2; ++np)
#pragma unroll
                for (int mt = 0; mt < 2; ++mt) {
                    float* d0 = acc[mt][np * 2];
                    float* d1 = acc[mt][np * 2 + 1];
                    unsigned* A = ahi[mt][k16];
                    unsigned* L = alo[mt][k16];
                    unsigned* H = wbhi[np][k16];
                    unsigned* Wl = wblo[np][k16];
                    mma_bf16(d0, A[0], A[1], A[2], A[3], H[0], H[1]);
                    mma_bf16(d1, A[0], A[1], A[2], A[3], H[2], H[3]);
                    mma_bf16(d0, A[0], A[1], A[2], A[3], Wl[0], Wl[1]);
                    mma_bf16(d1, A[0], A[1], A[2], A[3], Wl[2], Wl[3]);
                    mma_bf16(d0, L[0], L[1], L[2], L[3], H[0], H[1]);
                    mma_bf16(d1, L[0], L[1], L[2], L[3], H[2], H[3]);
                }

        // write warp partials: part[w][cc][b]
        {
            const int brow = lane >> 2;
            const int c0 = (lane & 3) * 2;
            float* pp = part + w * 1024;
#pragma unroll
            for (int mt = 0; mt < 2; ++mt)
#pragma unroll
                for (int nt = 0; nt < 4; ++nt) {
                    int cc = nt * 8 + c0;
                    int bb = mt * 16 + brow;
                    pp[cc * 32 + bb]            = acc[mt][nt][0];
                    pp[(cc + 1) * 32 + bb]      = acc[mt][nt][1];
                    pp[cc * 32 + bb + 8]        = acc[mt][nt][2];
                    pp[(cc + 1) * 32 + bb + 8]  = acc[mt][nt][3];
                }
        }
        __syncthreads();

        // epilogue: thread (u, b) computes cell update
        {
            float gate[4];
#pragma unroll
            for (int g = 0; g < 4; ++g) {
                float sum = xgv[g] + biasr[g];
                const float* pp = part + (g * 8 + u) * 32 + b;
#pragma unroll
                for (int sl = 0; sl < 8; ++sl) sum += pp[sl * 1024];
                gate[g] = sum;
            }
            float iv = 1.0f / (1.0f + __expf(-gate[0]));
            float fv = 1.0f / (1.0f + __expf(-gate[1]));
            float gv = tanhf(gate[2]);
            float ov = 1.0f / (1.0f + __expf(-gate[3]));
            cstate = fv * cstate + iv * gv;
            float hv = ov * tanhf(cstate);
            __nv_bfloat16 hhi = __float2bfloat16_rn(hv);
            __nv_bfloat16 hlo = __float2bfloat16_rn(hv - __bfloat162float(hhi));
            char* hd = g_hF[(s + 1) & 1][dir];
            *(__nv_bfloat16*)(hd + st_byte)         = hhi;
            *(__nv_bfloat16*)(hd + 32768 + st_byte) = hlo;
            psum[tid] = hv * wfc;
        }
        __syncthreads();
        // publish step completion (h writes ordered by syncthreads before release)
        if (tid == 64 && s + 1 < T_LEN)
            st_rel(&g_flag[dir][blk & 63], (unsigned)(s + 1));
        if (tid < 32) {
            float tot = 0.0f;
#pragma unroll
            for (int uu = 0; uu < 8; ++uu) tot += psum[tid + uu * 32];
            g_part[blk][t][tid] = tot;
        }
    }
}

// ---------------- kernel 5: reduce partials + sigmoid ----------------
__global__ void finalize_kernel(const float* __restrict__ b_fc, float* __restrict__ out) {
    int g = blockIdx.x * blockDim.x + threadIdx.x;
    if (g >= T_LEN * BATCH) return;
    int t = g >> 5, b = g & 31;
    float acc = b_fc[0];
    const float* p = &g_part[0][t][b];
#pragma unroll 8
    for (int blk = 0; blk < 128; ++blk)
        acc += p[(size_t)blk * T_LEN * BATCH];
    out[(size_t)b * T_LEN + t] = 1.0f / (1.0f + __expf(-acc));
}

// ---------------- launcher ----------------
extern "C" void kernel_launch(void* const* d_in, const int* in_sizes, int n_in,
                              void* d_out, int out_size) {
    const float* x    = (const float*)d_in[0];
    const float* Wx_f = (const float*)d_in[1];
    const float* Wh_f = (const float*)d_in[2];
    const float* b_f  = (const float*)d_in[3];
    const float* Wx_b = (const float*)d_in[4];
    const float* Wh_b = (const float*)d_in[5];
    const float* b_b  = (const float*)d_in[6];
    const float* Wfc  = (const float*)d_in[7];
    const float* bfc  = (const float*)d_in[8];
    float* out = (float*)d_out;
    (void)in_sizes; (void)n_in; (void)out_size;

    cudaFuncSetAttribute(mma_gemm_kernel, cudaFuncAttributeMaxDynamicSharedMemorySize, GSM_TOT);
    cudaFuncSetAttribute(lstm_kernel, cudaFuncAttributeMaxDynamicSharedMemorySize, LSM_TOT);

    zero_state_kernel<<<256, 256>>>();
    conv_x_kernel<<<ROWS * D_IN / 8 / 256, 256>>>(x);
    conv_w_kernel<<<dim3(NCOL / 32, D_IN / 32), 256>>>(Wx_f, Wx_b);
    mma_gemm_kernel<<<dim3(32, 256), 256, GSM_TOT>>>();
    lstm_kernel<<<128, 256, LSM_TOT>>>(Wh_f, Wh_b, b_f, b_b, Wfc);
    finalize_kernel<<<128, 256>>>(bfc, out);
}